// round 15
// baseline (speedup 1.0000x reference)
#include <cuda_runtime.h>
#include <cuda_fp16.h>
#include <math.h>

#define NB 8
#define C 192
#define C3 576
#define NH 4
#define CH 48
#define HH 128
#define WW 128
#define HW 16384
#define SPLIT 16
#define PART_STRIDE (CH*CH + 2*CH)   /* 2400 */

// Scratch (device globals: no allocation allowed in kernel_launch)
__device__ __half g_qkv[NB*C3*HW];                 // 151 MB
__device__ __half g_dw [NB*C3*HW];                 // 151 MB
__device__ float g_part[SPLIT*NB*NH*PART_STRIDE];
__device__ float g_score[NB*NH*CH*CH];
__device__ __half g_P  [NB*C*C];                   // fp16 fused projection

// ===========================================================================
// FP16 tensor-core GEMM (m16n8k16, fp32 accum).
// BM=64, BN=128, BK=32, 256 threads (8 warps 2x4), warp tile 32x32.
// ===========================================================================
#define GBM 64
#define GBN 128
#define GBK 32
#define KD  192
#define GNT (KD/GBK)   /* 6 */

__device__ __forceinline__ unsigned h2u(__half2 h) {
    return *(unsigned*)&h;
}
__device__ __forceinline__ void ldsm_x4(unsigned& r0, unsigned& r1, unsigned& r2,
                                        unsigned& r3, unsigned addr) {
    asm volatile("ldmatrix.sync.aligned.m8n8.x4.shared.b16 {%0,%1,%2,%3}, [%4];"
        : "=r"(r0), "=r"(r1), "=r"(r2), "=r"(r3) : "r"(addr));
}
__device__ __forceinline__ void ldsm_x4_t(unsigned& r0, unsigned& r1, unsigned& r2,
                                          unsigned& r3, unsigned addr) {
    asm volatile("ldmatrix.sync.aligned.m8n8.x4.trans.shared.b16 {%0,%1,%2,%3}, [%4];"
        : "=r"(r0), "=r"(r1), "=r"(r2), "=r"(r3) : "r"(addr));
}

#define MMA_F16(d, av, bv)                                                    \
  asm("mma.sync.aligned.m16n8k16.row.col.f32.f16.f16.f32 "                    \
      "{%0,%1,%2,%3}, {%4,%5,%6,%7}, {%8,%9}, {%0,%1,%2,%3};"                 \
      : "+f"(d[0]), "+f"(d[1]), "+f"(d[2]), "+f"(d[3])                        \
      : "r"(av[0]), "r"(av[1]), "r"(av[2]), "r"(av[3]),                       \
        "r"(bv[0]), "r"(bv[1]))

#define CP_ASYNC16(smem_u32, gptr)                                            \
  asm volatile("cp.async.ca.shared.global [%0], [%1], 16;"                    \
               :: "r"(smem_u32), "l"(gptr))
#define CP_COMMIT()  asm volatile("cp.async.commit_group;")
#define CP_WAIT0()   asm volatile("cp.async.wait_group 0;" ::: "memory")

// A smem chunk slot (uint4 index) for logical (m, chunk c in 0..3)
__device__ __forceinline__ int a_slot(int m, int c) {
    return (m >> 1) * 8 + ((((m & 1) << 2) + c) ^ ((m >> 1) & 7));
}
// B smem chunk slot for logical (k, chunk c in 0..15)
__device__ __forceinline__ int b_slot(int k, int c) {
    return k * 16 + (c ^ (k & 7));
}

#define GEMM_COMPUTE_F16(asbase_, bsbase_)                                    \
  do {                                                                        \
    _Pragma("unroll")                                                         \
    for (int kk = 0; kk < 2; kk++) {                                          \
        unsigned a[2][4], b[4][2];                                            \
        _Pragma("unroll")                                                     \
        for (int mi = 0; mi < 2; mi++) {                                      \
            int m = wm * 32 + mi * 16 + a_sel;                                \
            int c = 2 * kk + a_hi;                                            \
            ldsm_x4(a[mi][0], a[mi][1], a[mi][2], a[mi][3],                   \
                    (asbase_) + a_slot(m, c) * 16);                           \
        }                                                                     \
        _Pragma("unroll")                                                     \
        for (int np = 0; np < 2; np++) {                                      \
            int k = kk * 16 + b_koff;                                         \
            int cb = wn * 4 + 2 * np + b_nsel;                                \
            ldsm_x4_t(b[2*np][0], b[2*np][1], b[2*np+1][0], b[2*np+1][1],     \
                      (bsbase_) + b_slot(k, cb) * 16);                        \
        }                                                                     \
        _Pragma("unroll")                                                     \
        for (int mi = 0; mi < 2; mi++)                                        \
            _Pragma("unroll")                                                 \
            for (int ni = 0; ni < 4; ni++)                                    \
                MMA_F16(acc[mi][ni], a[mi], b[ni]);                           \
    }                                                                         \
  } while (0)

__device__ __forceinline__ uint4 pack8(float4 f0, float4 f1) {
    uint4 v;
    v.x = h2u(__floats2half2_rn(f0.x, f0.y));
    v.y = h2u(__floats2half2_rn(f0.z, f0.w));
    v.z = h2u(__floats2half2_rn(f1.x, f1.y));
    v.w = h2u(__floats2half2_rn(f1.z, f1.w));
    return v;
}

// sum of squares of the two halves packed in one register
__device__ __forceinline__ float sq2(unsigned u) {
    float2 f = __half22float2(*(__half2*)&u);
    return f.x * f.x + f.y * f.y;
}

// ---------------------------------------------------------------------------
// GEMM 1: A fp32 (shared weights), B fp32 (batched), C fp16.  (R11-proven)
// ---------------------------------------------------------------------------
__global__ __launch_bounds__(256) void gemm_f32b_h_kernel(
    const float* __restrict__ A, const float* __restrict__ Bm, __half* __restrict__ Cm,
    int M, int N, size_t bstride)
{
    __shared__ __align__(16) __half As[2][GBM * GBK];
    __shared__ __align__(16) __half Bs[2][GBK * GBN];

    const int tid  = threadIdx.x;
    const int lane = tid & 31, wid = tid >> 5;
    const int wm = wid & 1, wn = wid >> 1;
    const int g = lane >> 2, tig = lane & 3;
    const int a_sel = lane & 15, a_hi = lane >> 4;
    const int b_koff = lane & 15, b_nsel = lane >> 4;

    const int m0 = blockIdx.y * GBM, n0 = blockIdx.x * GBN;
    const float* Ab = A + (size_t)m0 * KD;
    const float* Bb = Bm + bstride * blockIdx.z + n0;
    __half*      Cb = Cm + (size_t)blockIdx.z * M * N;

    unsigned asbase[2] = { (unsigned)__cvta_generic_to_shared(As[0]),
                           (unsigned)__cvta_generic_to_shared(As[1]) };
    unsigned bsbase[2] = { (unsigned)__cvta_generic_to_shared(Bs[0]),
                           (unsigned)__cvta_generic_to_shared(Bs[1]) };
    uint4* As4[2] = { (uint4*)As[0], (uint4*)As[1] };
    uint4* Bs4[2] = { (uint4*)Bs[0], (uint4*)Bs[1] };

    float acc[2][4][4];
#pragma unroll
    for (int mi = 0; mi < 2; mi++)
#pragma unroll
        for (int ni = 0; ni < 4; ni++)
#pragma unroll
            for (int j = 0; j < 4; j++) acc[mi][ni][j] = 0.f;

    const int am = tid >> 2, ac = tid & 3;
    float4 ar0, ar1, br0[2], br1[2];

    ar0 = *(const float4*)&Ab[(size_t)am * KD + ac * 8];
    ar1 = *(const float4*)&Ab[(size_t)am * KD + ac * 8 + 4];
#pragma unroll
    for (int i = 0; i < 2; i++) {
        int idx = tid + i * 256, k = idx >> 4, c = idx & 15;
        br0[i] = *(const float4*)&Bb[(size_t)k * N + c * 8];
        br1[i] = *(const float4*)&Bb[(size_t)k * N + c * 8 + 4];
    }
    As4[0][a_slot(am, ac)] = pack8(ar0, ar1);
#pragma unroll
    for (int i = 0; i < 2; i++) {
        int idx = tid + i * 256, k = idx >> 4, c = idx & 15;
        Bs4[0][b_slot(k, c)] = pack8(br0[i], br1[i]);
    }
    __syncthreads();

#pragma unroll
    for (int t = 0; t < GNT; t++) {
        const int cur = t & 1;
        if (t + 1 < GNT) {
            int kofs = (t + 1) * GBK;
#pragma unroll
            for (int i = 0; i < 2; i++) {
                int idx = tid + i * 256, k = idx >> 4, c = idx & 15;
                br0[i] = *(const float4*)&Bb[(size_t)(kofs + k) * N + c * 8];
                br1[i] = *(const float4*)&Bb[(size_t)(kofs + k) * N + c * 8 + 4];
            }
            ar0 = *(const float4*)&Ab[(size_t)am * KD + kofs + ac * 8];
            ar1 = *(const float4*)&Ab[(size_t)am * KD + kofs + ac * 8 + 4];
        }

        GEMM_COMPUTE_F16(asbase[cur], bsbase[cur]);

        if (t + 1 < GNT) {
            const int nxt = cur ^ 1;
#pragma unroll
            for (int i = 0; i < 2; i++) {
                int idx = tid + i * 256, k = idx >> 4, c = idx & 15;
                Bs4[nxt][b_slot(k, c)] = pack8(br0[i], br1[i]);
            }
            As4[nxt][a_slot(am, ac)] = pack8(ar0, ar1);
            __syncthreads();
        }
    }

#pragma unroll
    for (int mi = 0; mi < 2; mi++) {
        int m = m0 + wm * 32 + mi * 16 + g;
#pragma unroll
        for (int ni = 0; ni < 4; ni++) {
            int n = n0 + wn * 32 + ni * 8 + tig * 2;
            *(__half2*)&Cb[(size_t)m * N + n] =
                __floats2half2_rn(acc[mi][ni][0], acc[mi][ni][1]);
            *(__half2*)&Cb[(size_t)(m + 8) * N + n] =
                __floats2half2_rn(acc[mi][ni][2], acc[mi][ni][3]);
        }
    }
}

// ---------------------------------------------------------------------------
// GEMM 2: A fp16, B fp16, C fp32 — 2-stage cp.async (R11-proven).
// ---------------------------------------------------------------------------
__global__ __launch_bounds__(256) void gemm_hh_f32c_kernel(
    const __half* __restrict__ A, const __half* __restrict__ Bm, float* __restrict__ Cm,
    int M, int N, size_t astride, size_t bstride)
{
    __shared__ __align__(16) __half As[2][GBM * GBK];
    __shared__ __align__(16) __half Bs[2][GBK * GBN];

    const int tid  = threadIdx.x;
    const int lane = tid & 31, wid = tid >> 5;
    const int wm = wid & 1, wn = wid >> 1;
    const int g = lane >> 2, tig = lane & 3;
    const int a_sel = lane & 15, a_hi = lane >> 4;
    const int b_koff = lane & 15, b_nsel = lane >> 4;

    const int m0 = blockIdx.y * GBM, n0 = blockIdx.x * GBN;
    const __half* Ab = A + astride * blockIdx.z + (size_t)m0 * KD;
    const __half* Bb = Bm + bstride * blockIdx.z + n0;
    float*        Cb = Cm + (size_t)blockIdx.z * M * N;

    unsigned asbase[2] = { (unsigned)__cvta_generic_to_shared(As[0]),
                           (unsigned)__cvta_generic_to_shared(As[1]) };
    unsigned bsbase[2] = { (unsigned)__cvta_generic_to_shared(Bs[0]),
                           (unsigned)__cvta_generic_to_shared(Bs[1]) };

    float acc[2][4][4];
#pragma unroll
    for (int mi = 0; mi < 2; mi++)
#pragma unroll
        for (int ni = 0; ni < 4; ni++)
#pragma unroll
            for (int j = 0; j < 4; j++) acc[mi][ni][j] = 0.f;

    const int am = tid >> 2, ac = tid & 3;

    CP_ASYNC16(asbase[0] + a_slot(am, ac) * 16, &Ab[(size_t)am * KD + ac * 8]);
#pragma unroll
    for (int i = 0; i < 2; i++) {
        int idx = tid + i * 256, k = idx >> 4, c = idx & 15;
        CP_ASYNC16(bsbase[0] + b_slot(k, c) * 16, &Bb[(size_t)k * N + c * 8]);
    }
    CP_COMMIT();
    CP_WAIT0();
    __syncthreads();

#pragma unroll
    for (int t = 0; t < GNT; t++) {
        const int cur = t & 1;
        if (t + 1 < GNT) {
            const int nxt = cur ^ 1;
            int kofs = (t + 1) * GBK;
            CP_ASYNC16(asbase[nxt] + a_slot(am, ac) * 16,
                       &Ab[(size_t)am * KD + kofs + ac * 8]);
#pragma unroll
            for (int i = 0; i < 2; i++) {
                int idx = tid + i * 256, k = idx >> 4, c = idx & 15;
                CP_ASYNC16(bsbase[nxt] + b_slot(k, c) * 16,
                           &Bb[(size_t)(kofs + k) * N + c * 8]);
            }
            CP_COMMIT();
        }

        GEMM_COMPUTE_F16(asbase[cur], bsbase[cur]);

        if (t + 1 < GNT) {
            CP_WAIT0();
            __syncthreads();
        }
    }

#pragma unroll
    for (int mi = 0; mi < 2; mi++) {
        int m = m0 + wm * 32 + mi * 16 + g;
#pragma unroll
        for (int ni = 0; ni < 4; ni++) {
            int n = n0 + wn * 32 + ni * 8 + tig * 2;
            *(float2*)&Cb[(size_t)m * N + n] =
                make_float2(acc[mi][ni][0], acc[mi][ni][1]);
            *(float2*)&Cb[(size_t)(m + 8) * N + n] =
                make_float2(acc[mi][ni][2], acc[mi][ni][3]);
        }
    }
}

// ---------------------------------------------------------------------------
// Depthwise 3x3 over a channel range (fp16 in/out, fp32 math). R11 body.
// ---------------------------------------------------------------------------
#define DWR 16
__global__ __launch_bounds__(256) void dw_kernel(
    const __half* __restrict__ in, __half* __restrict__ out,
    const float* __restrict__ wdw, int chanBase, int chanCount)
{
    const int band = blockIdx.x;
    const int b    = blockIdx.y / chanCount;
    const int ch   = chanBase + blockIdx.y % chanCount;
    const int bc   = b * C3 + ch;
    const int tid  = threadIdx.x;
    const int y0   = band * DWR;

    __shared__ float s[DWR + 2][WW + 12];
    const __half* base = in + (size_t)bc * HW;

    for (int i = tid; i < (DWR + 2) * 16; i += 256) {
        int r = i >> 4, c8 = i & 15;
        int yy = y0 - 1 + r;
        float4 v0 = make_float4(0.f, 0.f, 0.f, 0.f);
        float4 v1 = v0;
        if (yy >= 0 && yy < HH) {
            uint4 rv = *(const uint4*)(const void*)&base[yy * WW + c8 * 8];
            float2 f0 = __half22float2(*(__half2*)&rv.x);
            float2 f1 = __half22float2(*(__half2*)&rv.y);
            float2 f2 = __half22float2(*(__half2*)&rv.z);
            float2 f3 = __half22float2(*(__half2*)&rv.w);
            v0 = make_float4(f0.x, f0.y, f1.x, f1.y);
            v1 = make_float4(f2.x, f2.y, f3.x, f3.y);
        }
        *(float4*)&s[r][c8 * 8 + 4] = v0;
        *(float4*)&s[r][c8 * 8 + 8] = v1;
    }
    if (tid < DWR + 2) { s[tid][3] = 0.f; s[tid][WW + 4] = 0.f; }

    float w[9];
#pragma unroll
    for (int i = 0; i < 9; i++) w[i] = __ldg(&wdw[ch * 9 + i]);
    __syncthreads();

    const int lane = tid & 31;
    for (int r = tid >> 5; r < DWR; r += 8) {
        __half* orow = out + (size_t)bc * HW + (y0 + r) * WW;
#pragma unroll
        for (int j = 0; j < 4; j++) {
            int cc = lane + j * 32;
            float acc = 0.f;
#pragma unroll
            for (int dy = 0; dy < 3; dy++)
#pragma unroll
                for (int dx = 0; dx < 3; dx++)
                    acc += w[dy * 3 + dx] * s[r + dy][cc + 3 + dx];
            orow[cc] = __float2half_rn(acc);
        }
    }
}

// ---------------------------------------------------------------------------
// Score partials via fp16 MMA. SPLIT=16: 8 iters of 128 spatial.
// Sum-of-squares computed from MMA fragments (no smem re-read); occ target 2.
// ---------------------------------------------------------------------------
__device__ __forceinline__ int sc_slot(int r, int c) {  // [48 rows][16 chunks]
    return r * 16 + (c ^ (r & 7));
}

__global__ __launch_bounds__(256, 2) void score_mma_kernel(const __half* __restrict__ qkvd)
{
    const int split = blockIdx.x;
    const int unit  = blockIdx.y;
    const int b = unit >> 2, hd = unit & 3;
    const __half* qb = qkvd + ((size_t)b * C3 + hd * CH) * HW;
    const __half* kb = qb + (size_t)C * HW;

    __shared__ __align__(16) uint4 Qs[CH * 16];
    __shared__ __align__(16) uint4 Ks[CH * 16];
    __shared__ float S[CH][CH];
    __shared__ float qsum[CH], ksum[CH];

    const int tid = threadIdx.x, lane = tid & 31, wid = tid >> 5;
    const unsigned qbase = (unsigned)__cvta_generic_to_shared(Qs);
    const unsigned kbase = (unsigned)__cvta_generic_to_shared(Ks);

    for (int e = tid; e < CH * CH; e += 256) S[e / CH][e % CH] = 0.f;
    if (tid < CH) qsum[tid] = 0.f;
    else if (tid < 2 * CH) ksum[tid - CH] = 0.f;

    float acc[3][6][4];
#pragma unroll
    for (int mi = 0; mi < 3; mi++)
#pragma unroll
        for (int ni = 0; ni < 6; ni++)
#pragma unroll
            for (int j = 0; j < 4; j++) acc[mi][ni][j] = 0.f;
    float qsq[3][2] = {{0.f,0.f},{0.f,0.f},{0.f,0.f}};
    float ksq[3][2] = {{0.f,0.f},{0.f,0.f},{0.f,0.f}};

    const int c0 = 2 * wid;
    const int ra = lane & 15;
    const int ca = lane >> 4;
    const int rb = (lane & 7) + ((lane >> 4) << 3);
    const int cbo = (lane >> 3) & 1;

#pragma unroll
    for (int it = 0; it < 8; it++) {
        const int s0 = split * 1024 + it * 128;
        __syncthreads();
#pragma unroll
        for (int i = 0; i < 3; i++) {
            int idx = tid + i * 256, r = idx >> 4, c = idx & 15;
            Qs[sc_slot(r, c)] = *(const uint4*)(const void*)&qb[(size_t)r * HW + s0 + c * 8];
            Ks[sc_slot(r, c)] = *(const uint4*)(const void*)&kb[(size_t)r * HW + s0 + c * 8];
        }
        __syncthreads();

        unsigned a[3][4];
#pragma unroll
        for (int mi = 0; mi < 3; mi++) {
            int r = 16 * mi + ra, c = c0 + ca;
            ldsm_x4(a[mi][0], a[mi][1], a[mi][2], a[mi][3],
                    qbase + (unsigned)(sc_slot(r, c) * 16));
        }
        unsigned bf[6][2];
#pragma unroll
        for (int nj = 0; nj < 3; nj++) {
            int r = 16 * nj + rb, c = c0 + cbo;
            ldsm_x4(bf[2*nj][0], bf[2*nj][1], bf[2*nj+1][0], bf[2*nj+1][1],
                    kbase + (unsigned)(sc_slot(r, c) * 16));
        }

        // sum-of-squares from fragments (each element appears in exactly one
        // warp's fragments): rows lo = 16*t + lane>>2, hi = lo + 8.
#pragma unroll
        for (int mi = 0; mi < 3; mi++) {
            qsq[mi][0] += sq2(a[mi][0]) + sq2(a[mi][2]);
            qsq[mi][1] += sq2(a[mi][1]) + sq2(a[mi][3]);
        }
#pragma unroll
        for (int nj = 0; nj < 3; nj++) {
            ksq[nj][0] += sq2(bf[2*nj][0])   + sq2(bf[2*nj][1]);
            ksq[nj][1] += sq2(bf[2*nj+1][0]) + sq2(bf[2*nj+1][1]);
        }

#pragma unroll
        for (int mi = 0; mi < 3; mi++)
#pragma unroll
            for (int ni = 0; ni < 6; ni++)
                MMA_F16(acc[mi][ni], a[mi], bf[ni]);
    }

    __syncthreads();
    // cross-warp reduction of S
#pragma unroll
    for (int mi = 0; mi < 3; mi++)
#pragma unroll
        for (int ni = 0; ni < 6; ni++)
#pragma unroll
            for (int d = 0; d < 4; d++) {
                int m = 16 * mi + (lane >> 2) + 8 * (d >> 1);
                int n = 8 * ni + (lane & 3) * 2 + (d & 1);
                atomicAdd(&S[m][n], acc[mi][ni][d]);
            }
    // reduce sumsq: 4 lanes (lane&3) hold partials of the same row
#pragma unroll
    for (int t2 = 0; t2 < 3; t2++)
#pragma unroll
        for (int h = 0; h < 2; h++) {
            float vq = qsq[t2][h];
            vq += __shfl_xor_sync(0xffffffff, vq, 1);
            vq += __shfl_xor_sync(0xffffffff, vq, 2);
            float vk = ksq[t2][h];
            vk += __shfl_xor_sync(0xffffffff, vk, 1);
            vk += __shfl_xor_sync(0xffffffff, vk, 2);
            if ((lane & 3) == 0) {
                int row = 16 * t2 + 8 * h + (lane >> 2);
                atomicAdd(&qsum[row], vq);
                atomicAdd(&ksum[row], vk);
            }
        }
    __syncthreads();

    float* part = g_part + ((size_t)split * NB * NH + unit) * PART_STRIDE;
    for (int e = tid; e < CH * CH; e += 256) part[e] = S[e / CH][e % CH];
    if (tid < CH) part[CH * CH + tid] = qsum[tid];
    else if (tid < 2 * CH) part[CH * CH + tid] = ksum[tid - CH];
}

// ---------------------------------------------------------------------------
// Reduce partials, normalize + temperature + softmax. 32 blocks.
// ---------------------------------------------------------------------------
__global__ __launch_bounds__(256) void softmax_kernel(const float* __restrict__ temperature)
{
    int unit = blockIdx.x;
    int hd = unit & 3;
    __shared__ float S[CH][CH];
    __shared__ float rq[CH], rk[CH];
    int tid = threadIdx.x;

    for (int e = tid; e < CH * CH; e += 256) {
        float s = 0.f;
#pragma unroll
        for (int p = 0; p < SPLIT; p++)
            s += g_part[((size_t)p * NB * NH + unit) * PART_STRIDE + e];
        S[e / CH][e % CH] = s;
    }
    if (tid < 2 * CH) {
        float s = 0.f;
#pragma unroll
        for (int p = 0; p < SPLIT; p++)
            s += g_part[((size_t)p * NB * NH + unit) * PART_STRIDE + CH * CH + tid];
        float inv = 1.f / fmaxf(sqrtf(s), 1e-12f);
        if (tid < CH) rq[tid] = inv; else rk[tid - CH] = inv;
    }
    __syncthreads();

    float temp = temperature[hd];
    if (tid < CH) {
        int i = tid;
        float row[CH];
        float mx = -3.402823466e38f;
#pragma unroll
        for (int j = 0; j < CH; j++) {
            float v = S[i][j] * rq[i] * rk[j] * temp;
            row[j] = v;
            mx = fmaxf(mx, v);
        }
        float sum = 0.f;
#pragma unroll
        for (int j = 0; j < CH; j++) { row[j] = expf(row[j] - mx); sum += row[j]; }
        float inv = 1.f / sum;
#pragma unroll
        for (int j = 0; j < CH; j++)
            g_score[(size_t)unit * CH * CH + i * CH + j] = row[j] * inv;
    }
}

// ---------------------------------------------------------------------------
// P_b[o, hd*48+d] = sum_c Wproj[o, hd*48+c] * score[c][d]  -> fp16 output.
// ---------------------------------------------------------------------------
__global__ __launch_bounds__(256) void pmat_kernel(const float* __restrict__ wproj)
{
    int unit = blockIdx.x;
    int b = unit >> 2, hd = unit & 3;
    __shared__ float sc[CH][CH];
    __shared__ float wp[C][CH];
    int tid = threadIdx.x;

    for (int e = tid; e < CH * CH; e += 256)
        sc[e / CH][e % CH] = g_score[(size_t)unit * CH * CH + e];
    for (int e = tid; e < C * CH; e += 256) {
        int o = e / CH, c = e % CH;
        wp[o][c] = wproj[o * C + hd * CH + c];
    }
    __syncthreads();

    for (int e = tid; e < C * CH; e += 256) {
        int o = e / CH, d = e % CH;
        float acc = 0.f;
#pragma unroll
        for (int c = 0; c < CH; c++) acc += wp[o][c] * sc[c][d];
        g_P[((size_t)b * C + o) * C + hd * CH + d] = __float2half_rn(acc);
    }
}

// ---------------------------------------------------------------------------
extern "C" void kernel_launch(void* const* d_in, const int* in_sizes, int n_in,
                              void* d_out, int out_size)
{
    (void)in_sizes; (void)n_in; (void)out_size;
    const float* x      = (const float*)d_in[0];
    const float* w_qkv  = (const float*)d_in[1];
    const float* w_dw   = (const float*)d_in[2];
    const float* w_proj = (const float*)d_in[3];
    const float* temp   = (const float*)d_in[4];
    float* out = (float*)d_out;

    __half *qkv, *dwb, *pmat;
    cudaGetSymbolAddress((void**)&qkv,  g_qkv);
    cudaGetSymbolAddress((void**)&dwb,  g_dw);
    cudaGetSymbolAddress((void**)&pmat, g_P);

    // Fork a side stream for the v-channel depthwise branch.
    cudaStream_t s2;
    cudaStreamCreateWithFlags(&s2, cudaStreamNonBlocking);
    cudaEvent_t ev1, ev2;
    cudaEventCreateWithFlags(&ev1, cudaEventDisableTiming);
    cudaEventCreateWithFlags(&ev2, cudaEventDisableTiming);

    // 1) qkv = W_qkv (576x192) * x[b] (192x16384)
    gemm_f32b_h_kernel<<<dim3(HW / GBN, C3 / GBM, NB), 256>>>(
        w_qkv, x, qkv, C3, HW, (size_t)KD * HW);
    cudaEventRecord(ev1, 0);
    cudaStreamWaitEvent(s2, ev1, 0);

    // 2a) depthwise on q,k channels (main stream; feeds score)
    dw_kernel<<<dim3(HH / DWR, NB * 2 * C), 256>>>(qkv, dwb, w_dw, 0, 2 * C);
    // 2b) depthwise on v channels (side stream; feeds GEMM2 only)
    dw_kernel<<<dim3(HH / DWR, NB * C), 256, 0, s2>>>(qkv, dwb, w_dw, 2 * C, C);
    cudaEventRecord(ev2, s2);

    // 3) split-K score partials (fp16 MMA, SPLIT=16)
    score_mma_kernel<<<dim3(SPLIT, NB * NH), 256>>>(dwb);
    // 4) normalize + temperature + softmax
    softmax_kernel<<<NB * NH, 256>>>(temp);
    // 5) P_b = W_proj @ blockdiag(score_b)  (fp16 out)
    pmat_kernel<<<NB * NH, 256>>>(w_proj);

    // join: GEMM2 needs dw(v)
    cudaStreamWaitEvent(0, ev2, 0);
    // 6) out = P_b (192x192) * v[b] (192x16384)
    gemm_hh_f32c_kernel<<<dim3(HW / GBN, C / GBM, NB), 256>>>(
        pmat, dwb + (size_t)2 * C * HW, out, C, HW,
        (size_t)C * C, (size_t)C3 * HW);

    cudaEventDestroy(ev1);
    cudaEventDestroy(ev2);
    cudaStreamDestroy(s2);
}

// round 16
// speedup vs baseline: 1.0130x; 1.0130x over previous
#include <cuda_runtime.h>
#include <cuda_fp16.h>
#include <math.h>

#define NB 8
#define C 192
#define C3 576
#define NH 4
#define CH 48
#define HH 128
#define WW 128
#define HW 16384
#define SPLIT 16
#define PART_STRIDE (CH*CH + 2*CH)   /* 2400 */

// Scratch (device globals: no allocation allowed in kernel_launch)
__device__ __half g_qkv[NB*C3*HW];                 // 151 MB
__device__ __half g_dw [NB*C3*HW];                 // 151 MB
__device__ float g_part[SPLIT*NB*NH*PART_STRIDE];
__device__ float g_score[NB*NH*CH*CH];
__device__ __half g_P  [NB*C*C];                   // fp16 fused projection

// ===========================================================================
// FP16 tensor-core GEMM (m16n8k16, fp32 accum).
// BM=64, BN=128, BK=32, 256 threads (8 warps 2x4), warp tile 32x32.
// ===========================================================================
#define GBM 64
#define GBN 128
#define GBK 32
#define KD  192
#define GNT (KD/GBK)   /* 6 */

__device__ __forceinline__ unsigned h2u(__half2 h) {
    return *(unsigned*)&h;
}
__device__ __forceinline__ void ldsm_x4(unsigned& r0, unsigned& r1, unsigned& r2,
                                        unsigned& r3, unsigned addr) {
    asm volatile("ldmatrix.sync.aligned.m8n8.x4.shared.b16 {%0,%1,%2,%3}, [%4];"
        : "=r"(r0), "=r"(r1), "=r"(r2), "=r"(r3) : "r"(addr));
}
__device__ __forceinline__ void ldsm_x4_t(unsigned& r0, unsigned& r1, unsigned& r2,
                                          unsigned& r3, unsigned addr) {
    asm volatile("ldmatrix.sync.aligned.m8n8.x4.trans.shared.b16 {%0,%1,%2,%3}, [%4];"
        : "=r"(r0), "=r"(r1), "=r"(r2), "=r"(r3) : "r"(addr));
}

#define MMA_F16(d, av, bv)                                                    \
  asm("mma.sync.aligned.m16n8k16.row.col.f32.f16.f16.f32 "                    \
      "{%0,%1,%2,%3}, {%4,%5,%6,%7}, {%8,%9}, {%0,%1,%2,%3};"                 \
      : "+f"(d[0]), "+f"(d[1]), "+f"(d[2]), "+f"(d[3])                        \
      : "r"(av[0]), "r"(av[1]), "r"(av[2]), "r"(av[3]),                       \
        "r"(bv[0]), "r"(bv[1]))

#define CP_ASYNC16(smem_u32, gptr)                                            \
  asm volatile("cp.async.ca.shared.global [%0], [%1], 16;"                    \
               :: "r"(smem_u32), "l"(gptr))
#define CP_COMMIT()  asm volatile("cp.async.commit_group;")
#define CP_WAIT0()   asm volatile("cp.async.wait_group 0;" ::: "memory")

// A smem chunk slot (uint4 index) for logical (m, chunk c in 0..3)
__device__ __forceinline__ int a_slot(int m, int c) {
    return (m >> 1) * 8 + ((((m & 1) << 2) + c) ^ ((m >> 1) & 7));
}
// B smem chunk slot for logical (k, chunk c in 0..15)
__device__ __forceinline__ int b_slot(int k, int c) {
    return k * 16 + (c ^ (k & 7));
}

#define GEMM_COMPUTE_F16(asbase_, bsbase_)                                    \
  do {                                                                        \
    _Pragma("unroll")                                                         \
    for (int kk = 0; kk < 2; kk++) {                                          \
        unsigned a[2][4], b[4][2];                                            \
        _Pragma("unroll")                                                     \
        for (int mi = 0; mi < 2; mi++) {                                      \
            int m = wm * 32 + mi * 16 + a_sel;                                \
            int c = 2 * kk + a_hi;                                            \
            ldsm_x4(a[mi][0], a[mi][1], a[mi][2], a[mi][3],                   \
                    (asbase_) + a_slot(m, c) * 16);                           \
        }                                                                     \
        _Pragma("unroll")                                                     \
        for (int np = 0; np < 2; np++) {                                      \
            int k = kk * 16 + b_koff;                                         \
            int cb = wn * 4 + 2 * np + b_nsel;                                \
            ldsm_x4_t(b[2*np][0], b[2*np][1], b[2*np+1][0], b[2*np+1][1],     \
                      (bsbase_) + b_slot(k, cb) * 16);                        \
        }                                                                     \
        _Pragma("unroll")                                                     \
        for (int mi = 0; mi < 2; mi++)                                        \
            _Pragma("unroll")                                                 \
            for (int ni = 0; ni < 4; ni++)                                    \
                MMA_F16(acc[mi][ni], a[mi], b[ni]);                           \
    }                                                                         \
  } while (0)

__device__ __forceinline__ uint4 pack8(float4 f0, float4 f1) {
    uint4 v;
    v.x = h2u(__floats2half2_rn(f0.x, f0.y));
    v.y = h2u(__floats2half2_rn(f0.z, f0.w));
    v.z = h2u(__floats2half2_rn(f1.x, f1.y));
    v.w = h2u(__floats2half2_rn(f1.z, f1.w));
    return v;
}

// sum of squares of the two halves packed in one register
__device__ __forceinline__ float sq2(unsigned u) {
    float2 f = __half22float2(*(__half2*)&u);
    return f.x * f.x + f.y * f.y;
}
__device__ __forceinline__ float sq8(uint4 v) {
    return sq2(v.x) + sq2(v.y) + sq2(v.z) + sq2(v.w);
}

// ---------------------------------------------------------------------------
// GEMM 1: A fp32 (shared weights), B fp32 (batched), C fp16.  (R11-proven)
// ---------------------------------------------------------------------------
__global__ __launch_bounds__(256) void gemm_f32b_h_kernel(
    const float* __restrict__ A, const float* __restrict__ Bm, __half* __restrict__ Cm,
    int M, int N, size_t bstride)
{
    __shared__ __align__(16) __half As[2][GBM * GBK];
    __shared__ __align__(16) __half Bs[2][GBK * GBN];

    const int tid  = threadIdx.x;
    const int lane = tid & 31, wid = tid >> 5;
    const int wm = wid & 1, wn = wid >> 1;
    const int g = lane >> 2, tig = lane & 3;
    const int a_sel = lane & 15, a_hi = lane >> 4;
    const int b_koff = lane & 15, b_nsel = lane >> 4;

    const int m0 = blockIdx.y * GBM, n0 = blockIdx.x * GBN;
    const float* Ab = A + (size_t)m0 * KD;
    const float* Bb = Bm + bstride * blockIdx.z + n0;
    __half*      Cb = Cm + (size_t)blockIdx.z * M * N;

    unsigned asbase[2] = { (unsigned)__cvta_generic_to_shared(As[0]),
                           (unsigned)__cvta_generic_to_shared(As[1]) };
    unsigned bsbase[2] = { (unsigned)__cvta_generic_to_shared(Bs[0]),
                           (unsigned)__cvta_generic_to_shared(Bs[1]) };
    uint4* As4[2] = { (uint4*)As[0], (uint4*)As[1] };
    uint4* Bs4[2] = { (uint4*)Bs[0], (uint4*)Bs[1] };

    float acc[2][4][4];
#pragma unroll
    for (int mi = 0; mi < 2; mi++)
#pragma unroll
        for (int ni = 0; ni < 4; ni++)
#pragma unroll
            for (int j = 0; j < 4; j++) acc[mi][ni][j] = 0.f;

    const int am = tid >> 2, ac = tid & 3;
    float4 ar0, ar1, br0[2], br1[2];

    ar0 = *(const float4*)&Ab[(size_t)am * KD + ac * 8];
    ar1 = *(const float4*)&Ab[(size_t)am * KD + ac * 8 + 4];
#pragma unroll
    for (int i = 0; i < 2; i++) {
        int idx = tid + i * 256, k = idx >> 4, c = idx & 15;
        br0[i] = *(const float4*)&Bb[(size_t)k * N + c * 8];
        br1[i] = *(const float4*)&Bb[(size_t)k * N + c * 8 + 4];
    }
    As4[0][a_slot(am, ac)] = pack8(ar0, ar1);
#pragma unroll
    for (int i = 0; i < 2; i++) {
        int idx = tid + i * 256, k = idx >> 4, c = idx & 15;
        Bs4[0][b_slot(k, c)] = pack8(br0[i], br1[i]);
    }
    __syncthreads();

#pragma unroll
    for (int t = 0; t < GNT; t++) {
        const int cur = t & 1;
        if (t + 1 < GNT) {
            int kofs = (t + 1) * GBK;
#pragma unroll
            for (int i = 0; i < 2; i++) {
                int idx = tid + i * 256, k = idx >> 4, c = idx & 15;
                br0[i] = *(const float4*)&Bb[(size_t)(kofs + k) * N + c * 8];
                br1[i] = *(const float4*)&Bb[(size_t)(kofs + k) * N + c * 8 + 4];
            }
            ar0 = *(const float4*)&Ab[(size_t)am * KD + kofs + ac * 8];
            ar1 = *(const float4*)&Ab[(size_t)am * KD + kofs + ac * 8 + 4];
        }

        GEMM_COMPUTE_F16(asbase[cur], bsbase[cur]);

        if (t + 1 < GNT) {
            const int nxt = cur ^ 1;
#pragma unroll
            for (int i = 0; i < 2; i++) {
                int idx = tid + i * 256, k = idx >> 4, c = idx & 15;
                Bs4[nxt][b_slot(k, c)] = pack8(br0[i], br1[i]);
            }
            As4[nxt][a_slot(am, ac)] = pack8(ar0, ar1);
            __syncthreads();
        }
    }

#pragma unroll
    for (int mi = 0; mi < 2; mi++) {
        int m = m0 + wm * 32 + mi * 16 + g;
#pragma unroll
        for (int ni = 0; ni < 4; ni++) {
            int n = n0 + wn * 32 + ni * 8 + tig * 2;
            *(__half2*)&Cb[(size_t)m * N + n] =
                __floats2half2_rn(acc[mi][ni][0], acc[mi][ni][1]);
            *(__half2*)&Cb[(size_t)(m + 8) * N + n] =
                __floats2half2_rn(acc[mi][ni][2], acc[mi][ni][3]);
        }
    }
}

// ---------------------------------------------------------------------------
// GEMM 2: A fp16, B fp16, C fp32 — 2-stage cp.async (R11-proven).
// ---------------------------------------------------------------------------
__global__ __launch_bounds__(256) void gemm_hh_f32c_kernel(
    const __half* __restrict__ A, const __half* __restrict__ Bm, float* __restrict__ Cm,
    int M, int N, size_t astride, size_t bstride)
{
    __shared__ __align__(16) __half As[2][GBM * GBK];
    __shared__ __align__(16) __half Bs[2][GBK * GBN];

    const int tid  = threadIdx.x;
    const int lane = tid & 31, wid = tid >> 5;
    const int wm = wid & 1, wn = wid >> 1;
    const int g = lane >> 2, tig = lane & 3;
    const int a_sel = lane & 15, a_hi = lane >> 4;
    const int b_koff = lane & 15, b_nsel = lane >> 4;

    const int m0 = blockIdx.y * GBM, n0 = blockIdx.x * GBN;
    const __half* Ab = A + astride * blockIdx.z + (size_t)m0 * KD;
    const __half* Bb = Bm + bstride * blockIdx.z + n0;
    float*        Cb = Cm + (size_t)blockIdx.z * M * N;

    unsigned asbase[2] = { (unsigned)__cvta_generic_to_shared(As[0]),
                           (unsigned)__cvta_generic_to_shared(As[1]) };
    unsigned bsbase[2] = { (unsigned)__cvta_generic_to_shared(Bs[0]),
                           (unsigned)__cvta_generic_to_shared(Bs[1]) };

    float acc[2][4][4];
#pragma unroll
    for (int mi = 0; mi < 2; mi++)
#pragma unroll
        for (int ni = 0; ni < 4; ni++)
#pragma unroll
            for (int j = 0; j < 4; j++) acc[mi][ni][j] = 0.f;

    const int am = tid >> 2, ac = tid & 3;

    CP_ASYNC16(asbase[0] + a_slot(am, ac) * 16, &Ab[(size_t)am * KD + ac * 8]);
#pragma unroll
    for (int i = 0; i < 2; i++) {
        int idx = tid + i * 256, k = idx >> 4, c = idx & 15;
        CP_ASYNC16(bsbase[0] + b_slot(k, c) * 16, &Bb[(size_t)k * N + c * 8]);
    }
    CP_COMMIT();
    CP_WAIT0();
    __syncthreads();

#pragma unroll
    for (int t = 0; t < GNT; t++) {
        const int cur = t & 1;
        if (t + 1 < GNT) {
            const int nxt = cur ^ 1;
            int kofs = (t + 1) * GBK;
            CP_ASYNC16(asbase[nxt] + a_slot(am, ac) * 16,
                       &Ab[(size_t)am * KD + kofs + ac * 8]);
#pragma unroll
            for (int i = 0; i < 2; i++) {
                int idx = tid + i * 256, k = idx >> 4, c = idx & 15;
                CP_ASYNC16(bsbase[nxt] + b_slot(k, c) * 16,
                           &Bb[(size_t)(kofs + k) * N + c * 8]);
            }
            CP_COMMIT();
        }

        GEMM_COMPUTE_F16(asbase[cur], bsbase[cur]);

        if (t + 1 < GNT) {
            CP_WAIT0();
            __syncthreads();
        }
    }

#pragma unroll
    for (int mi = 0; mi < 2; mi++) {
        int m = m0 + wm * 32 + mi * 16 + g;
#pragma unroll
        for (int ni = 0; ni < 4; ni++) {
            int n = n0 + wn * 32 + ni * 8 + tig * 2;
            *(float2*)&Cb[(size_t)m * N + n] =
                make_float2(acc[mi][ni][0], acc[mi][ni][1]);
            *(float2*)&Cb[(size_t)(m + 8) * N + n] =
                make_float2(acc[mi][ni][2], acc[mi][ni][3]);
        }
    }
}

// ---------------------------------------------------------------------------
// Depthwise 3x3 over a channel range (fp16 in/out, fp32 math). R11 body.
// ---------------------------------------------------------------------------
#define DWR 16
__global__ __launch_bounds__(256) void dw_kernel(
    const __half* __restrict__ in, __half* __restrict__ out,
    const float* __restrict__ wdw, int chanBase, int chanCount)
{
    const int band = blockIdx.x;
    const int b    = blockIdx.y / chanCount;
    const int ch   = chanBase + blockIdx.y % chanCount;
    const int bc   = b * C3 + ch;
    const int tid  = threadIdx.x;
    const int y0   = band * DWR;

    __shared__ float s[DWR + 2][WW + 12];
    const __half* base = in + (size_t)bc * HW;

    for (int i = tid; i < (DWR + 2) * 16; i += 256) {
        int r = i >> 4, c8 = i & 15;
        int yy = y0 - 1 + r;
        float4 v0 = make_float4(0.f, 0.f, 0.f, 0.f);
        float4 v1 = v0;
        if (yy >= 0 && yy < HH) {
            uint4 rv = *(const uint4*)(const void*)&base[yy * WW + c8 * 8];
            float2 f0 = __half22float2(*(__half2*)&rv.x);
            float2 f1 = __half22float2(*(__half2*)&rv.y);
            float2 f2 = __half22float2(*(__half2*)&rv.z);
            float2 f3 = __half22float2(*(__half2*)&rv.w);
            v0 = make_float4(f0.x, f0.y, f1.x, f1.y);
            v1 = make_float4(f2.x, f2.y, f3.x, f3.y);
        }
        *(float4*)&s[r][c8 * 8 + 4] = v0;
        *(float4*)&s[r][c8 * 8 + 8] = v1;
    }
    if (tid < DWR + 2) { s[tid][3] = 0.f; s[tid][WW + 4] = 0.f; }

    float w[9];
#pragma unroll
    for (int i = 0; i < 9; i++) w[i] = __ldg(&wdw[ch * 9 + i]);
    __syncthreads();

    const int lane = tid & 31;
    for (int r = tid >> 5; r < DWR; r += 8) {
        __half* orow = out + (size_t)bc * HW + (y0 + r) * WW;
#pragma unroll
        for (int j = 0; j < 4; j++) {
            int cc = lane + j * 32;
            float acc = 0.f;
#pragma unroll
            for (int dy = 0; dy < 3; dy++)
#pragma unroll
                for (int dx = 0; dx < 3; dx++)
                    acc += w[dy * 3 + dx] * s[r + dy][cc + 3 + dx];
            orow[cc] = __float2half_rn(acc);
        }
    }
}

// ---------------------------------------------------------------------------
// Score partials via fp16 MMA. SPLIT=16: 8 iters of 128 spatial.
// Sum-of-squares computed on the GLOBAL-LOAD registers (rows fixed per
// (tid,i) across iterations -> 3+3 local accumulators, 6 atomics at end).
// ---------------------------------------------------------------------------
__device__ __forceinline__ int sc_slot(int r, int c) {  // [48 rows][16 chunks]
    return r * 16 + (c ^ (r & 7));
}

__global__ __launch_bounds__(256) void score_mma_kernel(const __half* __restrict__ qkvd)
{
    const int split = blockIdx.x;
    const int unit  = blockIdx.y;
    const int b = unit >> 2, hd = unit & 3;
    const __half* qb = qkvd + ((size_t)b * C3 + hd * CH) * HW;
    const __half* kb = qb + (size_t)C * HW;

    __shared__ __align__(16) uint4 Qs[CH * 16];
    __shared__ __align__(16) uint4 Ks[CH * 16];
    __shared__ float S[CH][CH];
    __shared__ float qsum[CH], ksum[CH];

    const int tid = threadIdx.x, lane = tid & 31, wid = tid >> 5;
    const unsigned qbase = (unsigned)__cvta_generic_to_shared(Qs);
    const unsigned kbase = (unsigned)__cvta_generic_to_shared(Ks);

    for (int e = tid; e < CH * CH; e += 256) S[e / CH][e % CH] = 0.f;
    if (tid < CH) qsum[tid] = 0.f;
    else if (tid < 2 * CH) ksum[tid - CH] = 0.f;

    float acc[3][6][4];
#pragma unroll
    for (int mi = 0; mi < 3; mi++)
#pragma unroll
        for (int ni = 0; ni < 6; ni++)
#pragma unroll
            for (int j = 0; j < 4; j++) acc[mi][ni][j] = 0.f;
    float qsql[3] = {0.f, 0.f, 0.f};
    float ksql[3] = {0.f, 0.f, 0.f};

    const int c0 = 2 * wid;
    const int ra = lane & 15;
    const int ca = lane >> 4;
    const int rb = (lane & 7) + ((lane >> 4) << 3);
    const int cbo = (lane >> 3) & 1;

#pragma unroll
    for (int it = 0; it < 8; it++) {
        const int s0 = split * 1024 + it * 128;
        __syncthreads();
#pragma unroll
        for (int i = 0; i < 3; i++) {
            int idx = tid + i * 256, r = idx >> 4, c = idx & 15;
            uint4 qv = *(const uint4*)(const void*)&qb[(size_t)r * HW + s0 + c * 8];
            uint4 kv = *(const uint4*)(const void*)&kb[(size_t)r * HW + s0 + c * 8];
            Qs[sc_slot(r, c)] = qv;
            Ks[sc_slot(r, c)] = kv;
            qsql[i] += sq8(qv);
            ksql[i] += sq8(kv);
        }
        __syncthreads();

        unsigned a[3][4];
#pragma unroll
        for (int mi = 0; mi < 3; mi++) {
            int r = 16 * mi + ra, c = c0 + ca;
            ldsm_x4(a[mi][0], a[mi][1], a[mi][2], a[mi][3],
                    qbase + (unsigned)(sc_slot(r, c) * 16));
        }
        unsigned bf[6][2];
#pragma unroll
        for (int nj = 0; nj < 3; nj++) {
            int r = 16 * nj + rb, c = c0 + cbo;
            ldsm_x4(bf[2*nj][0], bf[2*nj][1], bf[2*nj+1][0], bf[2*nj+1][1],
                    kbase + (unsigned)(sc_slot(r, c) * 16));
        }
#pragma unroll
        for (int mi = 0; mi < 3; mi++)
#pragma unroll
            for (int ni = 0; ni < 6; ni++)
                MMA_F16(acc[mi][ni], a[mi], bf[ni]);
    }

    __syncthreads();
    // cross-warp reduction of S
#pragma unroll
    for (int mi = 0; mi < 3; mi++)
#pragma unroll
        for (int ni = 0; ni < 6; ni++)
#pragma unroll
            for (int d = 0; d < 4; d++) {
                int m = 16 * mi + (lane >> 2) + 8 * (d >> 1);
                int n = 8 * ni + (lane & 3) * 2 + (d & 1);
                atomicAdd(&S[m][n], acc[mi][ni][d]);
            }
    // sumsq: row for slot (tid, i) is fixed -> 6 atomics per thread
#pragma unroll
    for (int i = 0; i < 3; i++) {
        int r = (tid + i * 256) >> 4;
        atomicAdd(&qsum[r], qsql[i]);
        atomicAdd(&ksum[r], ksql[i]);
    }
    __syncthreads();

    float* part = g_part + ((size_t)split * NB * NH + unit) * PART_STRIDE;
    for (int e = tid; e < CH * CH; e += 256) part[e] = S[e / CH][e % CH];
    if (tid < CH) part[CH * CH + tid] = qsum[tid];
    else if (tid < 2 * CH) part[CH * CH + tid] = ksum[tid - CH];
}

// ---------------------------------------------------------------------------
// Reduce partials, normalize + temperature + softmax. 32 blocks.
// ---------------------------------------------------------------------------
__global__ __launch_bounds__(256) void softmax_kernel(const float* __restrict__ temperature)
{
    int unit = blockIdx.x;
    int hd = unit & 3;
    __shared__ float S[CH][CH];
    __shared__ float rq[CH], rk[CH];
    int tid = threadIdx.x;

    for (int e = tid; e < CH * CH; e += 256) {
        float s = 0.f;
#pragma unroll
        for (int p = 0; p < SPLIT; p++)
            s += g_part[((size_t)p * NB * NH + unit) * PART_STRIDE + e];
        S[e / CH][e % CH] = s;
    }
    if (tid < 2 * CH) {
        float s = 0.f;
#pragma unroll
        for (int p = 0; p < SPLIT; p++)
            s += g_part[((size_t)p * NB * NH + unit) * PART_STRIDE + CH * CH + tid];
        float inv = 1.f / fmaxf(sqrtf(s), 1e-12f);
        if (tid < CH) rq[tid] = inv; else rk[tid - CH] = inv;
    }
    __syncthreads();

    float temp = temperature[hd];
    if (tid < CH) {
        int i = tid;
        float row[CH];
        float mx = -3.402823466e38f;
#pragma unroll
        for (int j = 0; j < CH; j++) {
            float v = S[i][j] * rq[i] * rk[j] * temp;
            row[j] = v;
            mx = fmaxf(mx, v);
        }
        float sum = 0.f;
#pragma unroll
        for (int j = 0; j < CH; j++) { row[j] = expf(row[j] - mx); sum += row[j]; }
        float inv = 1.f / sum;
#pragma unroll
        for (int j = 0; j < CH; j++)
            g_score[(size_t)unit * CH * CH + i * CH + j] = row[j] * inv;
    }
}

// ---------------------------------------------------------------------------
// P_b[o, hd*48+d] = sum_c Wproj[o, hd*48+c] * score[c][d]  -> fp16 output.
// ---------------------------------------------------------------------------
__global__ __launch_bounds__(256) void pmat_kernel(const float* __restrict__ wproj)
{
    int unit = blockIdx.x;
    int b = unit >> 2, hd = unit & 3;
    __shared__ float sc[CH][CH];
    __shared__ float wp[C][CH];
    int tid = threadIdx.x;

    for (int e = tid; e < CH * CH; e += 256)
        sc[e / CH][e % CH] = g_score[(size_t)unit * CH * CH + e];
    for (int e = tid; e < C * CH; e += 256) {
        int o = e / CH, c = e % CH;
        wp[o][c] = wproj[o * C + hd * CH + c];
    }
    __syncthreads();

    for (int e = tid; e < C * CH; e += 256) {
        int o = e / CH, d = e % CH;
        float acc = 0.f;
#pragma unroll
        for (int c = 0; c < CH; c++) acc += wp[o][c] * sc[c][d];
        g_P[((size_t)b * C + o) * C + hd * CH + d] = __float2half_rn(acc);
    }
}

// ---------------------------------------------------------------------------
extern "C" void kernel_launch(void* const* d_in, const int* in_sizes, int n_in,
                              void* d_out, int out_size)
{
    (void)in_sizes; (void)n_in; (void)out_size;
    const float* x      = (const float*)d_in[0];
    const float* w_qkv  = (const float*)d_in[1];
    const float* w_dw   = (const float*)d_in[2];
    const float* w_proj = (const float*)d_in[3];
    const float* temp   = (const float*)d_in[4];
    float* out = (float*)d_out;

    __half *qkv, *dwb, *pmat;
    cudaGetSymbolAddress((void**)&qkv,  g_qkv);
    cudaGetSymbolAddress((void**)&dwb,  g_dw);
    cudaGetSymbolAddress((void**)&pmat, g_P);

    // Fork a side stream for the v-channel depthwise branch.
    cudaStream_t s2;
    cudaStreamCreateWithFlags(&s2, cudaStreamNonBlocking);
    cudaEvent_t ev1, ev2;
    cudaEventCreateWithFlags(&ev1, cudaEventDisableTiming);
    cudaEventCreateWithFlags(&ev2, cudaEventDisableTiming);

    // 1) qkv = W_qkv (576x192) * x[b] (192x16384)
    gemm_f32b_h_kernel<<<dim3(HW / GBN, C3 / GBM, NB), 256>>>(
        w_qkv, x, qkv, C3, HW, (size_t)KD * HW);
    cudaEventRecord(ev1, 0);
    cudaStreamWaitEvent(s2, ev1, 0);

    // 2a) depthwise on q,k channels (main stream; feeds score)
    dw_kernel<<<dim3(HH / DWR, NB * 2 * C), 256>>>(qkv, dwb, w_dw, 0, 2 * C);
    // 2b) depthwise on v channels (side stream; feeds GEMM2 only)
    dw_kernel<<<dim3(HH / DWR, NB * C), 256, 0, s2>>>(qkv, dwb, w_dw, 2 * C, C);
    cudaEventRecord(ev2, s2);

    // 3) split-K score partials (fp16 MMA, SPLIT=16)
    score_mma_kernel<<<dim3(SPLIT, NB * NH), 256>>>(dwb);
    // 4) normalize + temperature + softmax
    softmax_kernel<<<NB * NH, 256>>>(temp);
    // 5) P_b = W_proj @ blockdiag(score_b)  (fp16 out)
    pmat_kernel<<<NB * NH, 256>>>(w_proj);

    // join: GEMM2 needs dw(v)
    cudaStreamWaitEvent(0, ev2, 0);
    // 6) out = P_b (192x192) * v[b] (192x16384)
    gemm_hh_f32c_kernel<<<dim3(HW / GBN, C / GBM, NB), 256>>>(
        pmat, dwb + (size_t)2 * C * HW, out, C, HW,
        (size_t)C * C, (size_t)C3 * HW);

    cudaEventDestroy(ev1);
    cudaEventDestroy(ev2);
    cudaStreamDestroy(s2);
}

// round 17
// speedup vs baseline: 1.0398x; 1.0264x over previous
#include <cuda_runtime.h>
#include <cuda_fp16.h>
#include <math.h>

#define NB 8
#define C 192
#define C3 576
#define NH 4
#define CH 48
#define HH 128
#define WW 128
#define HW 16384
#define SPLIT 16
#define PART_STRIDE (CH*CH)          /* 2304: scores only */
#define NBANDS 8                     /* HH / DWR */

// Scratch (device globals: no allocation allowed in kernel_launch)
__device__ __half g_qkv[NB*C3*HW];                 // 151 MB
__device__ __half g_dw [NB*C3*HW];                 // 151 MB
__device__ float g_part[SPLIT*NB*NH*PART_STRIDE];
__device__ float g_score[NB*NH*CH*CH];
__device__ float g_normp[NB*2*C*NBANDS];           // per-(b,ch,band) sumsq of dw(q,k)
__device__ __half g_P  [NB*C*C];                   // fp16 fused projection

// ===========================================================================
// FP16 tensor-core GEMM (m16n8k16, fp32 accum).
// BM=64, BN=128, BK=32, 256 threads (8 warps 2x4), warp tile 32x32.
// ===========================================================================
#define GBM 64
#define GBN 128
#define GBK 32
#define KD  192
#define GNT (KD/GBK)   /* 6 */

__device__ __forceinline__ unsigned h2u(__half2 h) {
    return *(unsigned*)&h;
}
__device__ __forceinline__ void ldsm_x4(unsigned& r0, unsigned& r1, unsigned& r2,
                                        unsigned& r3, unsigned addr) {
    asm volatile("ldmatrix.sync.aligned.m8n8.x4.shared.b16 {%0,%1,%2,%3}, [%4];"
        : "=r"(r0), "=r"(r1), "=r"(r2), "=r"(r3) : "r"(addr));
}
__device__ __forceinline__ void ldsm_x4_t(unsigned& r0, unsigned& r1, unsigned& r2,
                                          unsigned& r3, unsigned addr) {
    asm volatile("ldmatrix.sync.aligned.m8n8.x4.trans.shared.b16 {%0,%1,%2,%3}, [%4];"
        : "=r"(r0), "=r"(r1), "=r"(r2), "=r"(r3) : "r"(addr));
}

#define MMA_F16(d, av, bv)                                                    \
  asm("mma.sync.aligned.m16n8k16.row.col.f32.f16.f16.f32 "                    \
      "{%0,%1,%2,%3}, {%4,%5,%6,%7}, {%8,%9}, {%0,%1,%2,%3};"                 \
      : "+f"(d[0]), "+f"(d[1]), "+f"(d[2]), "+f"(d[3])                        \
      : "r"(av[0]), "r"(av[1]), "r"(av[2]), "r"(av[3]),                       \
        "r"(bv[0]), "r"(bv[1]))

#define CP_ASYNC16(smem_u32, gptr)                                            \
  asm volatile("cp.async.ca.shared.global [%0], [%1], 16;"                    \
               :: "r"(smem_u32), "l"(gptr))
#define CP_COMMIT()  asm volatile("cp.async.commit_group;")
#define CP_WAIT0()   asm volatile("cp.async.wait_group 0;" ::: "memory")

// A smem chunk slot (uint4 index) for logical (m, chunk c in 0..3)
__device__ __forceinline__ int a_slot(int m, int c) {
    return (m >> 1) * 8 + ((((m & 1) << 2) + c) ^ ((m >> 1) & 7));
}
// B smem chunk slot for logical (k, chunk c in 0..15)
__device__ __forceinline__ int b_slot(int k, int c) {
    return k * 16 + (c ^ (k & 7));
}

#define GEMM_COMPUTE_F16(asbase_, bsbase_)                                    \
  do {                                                                        \
    _Pragma("unroll")                                                         \
    for (int kk = 0; kk < 2; kk++) {                                          \
        unsigned a[2][4], b[4][2];                                            \
        _Pragma("unroll")                                                     \
        for (int mi = 0; mi < 2; mi++) {                                      \
            int m = wm * 32 + mi * 16 + a_sel;                                \
            int c = 2 * kk + a_hi;                                            \
            ldsm_x4(a[mi][0], a[mi][1], a[mi][2], a[mi][3],                   \
                    (asbase_) + a_slot(m, c) * 16);                           \
        }                                                                     \
        _Pragma("unroll")                                                     \
        for (int np = 0; np < 2; np++) {                                      \
            int k = kk * 16 + b_koff;                                         \
            int cb = wn * 4 + 2 * np + b_nsel;                                \
            ldsm_x4_t(b[2*np][0], b[2*np][1], b[2*np+1][0], b[2*np+1][1],     \
                      (bsbase_) + b_slot(k, cb) * 16);                        \
        }                                                                     \
        _Pragma("unroll")                                                     \
        for (int mi = 0; mi < 2; mi++)                                        \
            _Pragma("unroll")                                                 \
            for (int ni = 0; ni < 4; ni++)                                    \
                MMA_F16(acc[mi][ni], a[mi], b[ni]);                           \
    }                                                                         \
  } while (0)

__device__ __forceinline__ uint4 pack8(float4 f0, float4 f1) {
    uint4 v;
    v.x = h2u(__floats2half2_rn(f0.x, f0.y));
    v.y = h2u(__floats2half2_rn(f0.z, f0.w));
    v.z = h2u(__floats2half2_rn(f1.x, f1.y));
    v.w = h2u(__floats2half2_rn(f1.z, f1.w));
    return v;
}

// ---------------------------------------------------------------------------
// GEMM 1: A fp32 (shared weights), B fp32 (batched), C fp16.  (R11-proven)
// ---------------------------------------------------------------------------
__global__ __launch_bounds__(256) void gemm_f32b_h_kernel(
    const float* __restrict__ A, const float* __restrict__ Bm, __half* __restrict__ Cm,
    int M, int N, size_t bstride)
{
    __shared__ __align__(16) __half As[2][GBM * GBK];
    __shared__ __align__(16) __half Bs[2][GBK * GBN];

    const int tid  = threadIdx.x;
    const int lane = tid & 31, wid = tid >> 5;
    const int wm = wid & 1, wn = wid >> 1;
    const int g = lane >> 2, tig = lane & 3;
    const int a_sel = lane & 15, a_hi = lane >> 4;
    const int b_koff = lane & 15, b_nsel = lane >> 4;

    const int m0 = blockIdx.y * GBM, n0 = blockIdx.x * GBN;
    const float* Ab = A + (size_t)m0 * KD;
    const float* Bb = Bm + bstride * blockIdx.z + n0;
    __half*      Cb = Cm + (size_t)blockIdx.z * M * N;

    unsigned asbase[2] = { (unsigned)__cvta_generic_to_shared(As[0]),
                           (unsigned)__cvta_generic_to_shared(As[1]) };
    unsigned bsbase[2] = { (unsigned)__cvta_generic_to_shared(Bs[0]),
                           (unsigned)__cvta_generic_to_shared(Bs[1]) };
    uint4* As4[2] = { (uint4*)As[0], (uint4*)As[1] };
    uint4* Bs4[2] = { (uint4*)Bs[0], (uint4*)Bs[1] };

    float acc[2][4][4];
#pragma unroll
    for (int mi = 0; mi < 2; mi++)
#pragma unroll
        for (int ni = 0; ni < 4; ni++)
#pragma unroll
            for (int j = 0; j < 4; j++) acc[mi][ni][j] = 0.f;

    const int am = tid >> 2, ac = tid & 3;
    float4 ar0, ar1, br0[2], br1[2];

    ar0 = *(const float4*)&Ab[(size_t)am * KD + ac * 8];
    ar1 = *(const float4*)&Ab[(size_t)am * KD + ac * 8 + 4];
#pragma unroll
    for (int i = 0; i < 2; i++) {
        int idx = tid + i * 256, k = idx >> 4, c = idx & 15;
        br0[i] = *(const float4*)&Bb[(size_t)k * N + c * 8];
        br1[i] = *(const float4*)&Bb[(size_t)k * N + c * 8 + 4];
    }
    As4[0][a_slot(am, ac)] = pack8(ar0, ar1);
#pragma unroll
    for (int i = 0; i < 2; i++) {
        int idx = tid + i * 256, k = idx >> 4, c = idx & 15;
        Bs4[0][b_slot(k, c)] = pack8(br0[i], br1[i]);
    }
    __syncthreads();

#pragma unroll
    for (int t = 0; t < GNT; t++) {
        const int cur = t & 1;
        if (t + 1 < GNT) {
            int kofs = (t + 1) * GBK;
#pragma unroll
            for (int i = 0; i < 2; i++) {
                int idx = tid + i * 256, k = idx >> 4, c = idx & 15;
                br0[i] = *(const float4*)&Bb[(size_t)(kofs + k) * N + c * 8];
                br1[i] = *(const float4*)&Bb[(size_t)(kofs + k) * N + c * 8 + 4];
            }
            ar0 = *(const float4*)&Ab[(size_t)am * KD + kofs + ac * 8];
            ar1 = *(const float4*)&Ab[(size_t)am * KD + kofs + ac * 8 + 4];
        }

        GEMM_COMPUTE_F16(asbase[cur], bsbase[cur]);

        if (t + 1 < GNT) {
            const int nxt = cur ^ 1;
#pragma unroll
            for (int i = 0; i < 2; i++) {
                int idx = tid + i * 256, k = idx >> 4, c = idx & 15;
                Bs4[nxt][b_slot(k, c)] = pack8(br0[i], br1[i]);
            }
            As4[nxt][a_slot(am, ac)] = pack8(ar0, ar1);
            __syncthreads();
        }
    }

#pragma unroll
    for (int mi = 0; mi < 2; mi++) {
        int m = m0 + wm * 32 + mi * 16 + g;
#pragma unroll
        for (int ni = 0; ni < 4; ni++) {
            int n = n0 + wn * 32 + ni * 8 + tig * 2;
            *(__half2*)&Cb[(size_t)m * N + n] =
                __floats2half2_rn(acc[mi][ni][0], acc[mi][ni][1]);
            *(__half2*)&Cb[(size_t)(m + 8) * N + n] =
                __floats2half2_rn(acc[mi][ni][2], acc[mi][ni][3]);
        }
    }
}

// ---------------------------------------------------------------------------
// GEMM 2: A fp16, B fp16, C fp32 — 2-stage cp.async (R11-proven).
// ---------------------------------------------------------------------------
__global__ __launch_bounds__(256) void gemm_hh_f32c_kernel(
    const __half* __restrict__ A, const __half* __restrict__ Bm, float* __restrict__ Cm,
    int M, int N, size_t astride, size_t bstride)
{
    __shared__ __align__(16) __half As[2][GBM * GBK];
    __shared__ __align__(16) __half Bs[2][GBK * GBN];

    const int tid  = threadIdx.x;
    const int lane = tid & 31, wid = tid >> 5;
    const int wm = wid & 1, wn = wid >> 1;
    const int g = lane >> 2, tig = lane & 3;
    const int a_sel = lane & 15, a_hi = lane >> 4;
    const int b_koff = lane & 15, b_nsel = lane >> 4;

    const int m0 = blockIdx.y * GBM, n0 = blockIdx.x * GBN;
    const __half* Ab = A + astride * blockIdx.z + (size_t)m0 * KD;
    const __half* Bb = Bm + bstride * blockIdx.z + n0;
    float*        Cb = Cm + (size_t)blockIdx.z * M * N;

    unsigned asbase[2] = { (unsigned)__cvta_generic_to_shared(As[0]),
                           (unsigned)__cvta_generic_to_shared(As[1]) };
    unsigned bsbase[2] = { (unsigned)__cvta_generic_to_shared(Bs[0]),
                           (unsigned)__cvta_generic_to_shared(Bs[1]) };

    float acc[2][4][4];
#pragma unroll
    for (int mi = 0; mi < 2; mi++)
#pragma unroll
        for (int ni = 0; ni < 4; ni++)
#pragma unroll
            for (int j = 0; j < 4; j++) acc[mi][ni][j] = 0.f;

    const int am = tid >> 2, ac = tid & 3;

    CP_ASYNC16(asbase[0] + a_slot(am, ac) * 16, &Ab[(size_t)am * KD + ac * 8]);
#pragma unroll
    for (int i = 0; i < 2; i++) {
        int idx = tid + i * 256, k = idx >> 4, c = idx & 15;
        CP_ASYNC16(bsbase[0] + b_slot(k, c) * 16, &Bb[(size_t)k * N + c * 8]);
    }
    CP_COMMIT();
    CP_WAIT0();
    __syncthreads();

#pragma unroll
    for (int t = 0; t < GNT; t++) {
        const int cur = t & 1;
        if (t + 1 < GNT) {
            const int nxt = cur ^ 1;
            int kofs = (t + 1) * GBK;
            CP_ASYNC16(asbase[nxt] + a_slot(am, ac) * 16,
                       &Ab[(size_t)am * KD + kofs + ac * 8]);
#pragma unroll
            for (int i = 0; i < 2; i++) {
                int idx = tid + i * 256, k = idx >> 4, c = idx & 15;
                CP_ASYNC16(bsbase[nxt] + b_slot(k, c) * 16,
                           &Bb[(size_t)(kofs + k) * N + c * 8]);
            }
            CP_COMMIT();
        }

        GEMM_COMPUTE_F16(asbase[cur], bsbase[cur]);

        if (t + 1 < GNT) {
            CP_WAIT0();
            __syncthreads();
        }
    }

#pragma unroll
    for (int mi = 0; mi < 2; mi++) {
        int m = m0 + wm * 32 + mi * 16 + g;
#pragma unroll
        for (int ni = 0; ni < 4; ni++) {
            int n = n0 + wn * 32 + ni * 8 + tig * 2;
            *(float2*)&Cb[(size_t)m * N + n] =
                make_float2(acc[mi][ni][0], acc[mi][ni][1]);
            *(float2*)&Cb[(size_t)(m + 8) * N + n] =
                make_float2(acc[mi][ni][2], acc[mi][ni][3]);
        }
    }
}

// ---------------------------------------------------------------------------
// Depthwise 3x3 over a channel range (fp16 in/out, fp32 math). R11 body,
// plus optional per-(channel,band) sum-of-squares of the outputs (wantNorm).
// ---------------------------------------------------------------------------
#define DWR 16
__global__ __launch_bounds__(256) void dw_kernel(
    const __half* __restrict__ in, __half* __restrict__ out,
    const float* __restrict__ wdw, int chanBase, int chanCount, int wantNorm)
{
    const int band = blockIdx.x;
    const int b    = blockIdx.y / chanCount;
    const int chL  = blockIdx.y % chanCount;          // channel within range
    const int ch   = chanBase + chL;
    const int bc   = b * C3 + ch;
    const int tid  = threadIdx.x;
    const int y0   = band * DWR;

    __shared__ float s[DWR + 2][WW + 12];
    __shared__ float wred[8];
    const __half* base = in + (size_t)bc * HW;

    for (int i = tid; i < (DWR + 2) * 16; i += 256) {
        int r = i >> 4, c8 = i & 15;
        int yy = y0 - 1 + r;
        float4 v0 = make_float4(0.f, 0.f, 0.f, 0.f);
        float4 v1 = v0;
        if (yy >= 0 && yy < HH) {
            uint4 rv = *(const uint4*)(const void*)&base[yy * WW + c8 * 8];
            float2 f0 = __half22float2(*(__half2*)&rv.x);
            float2 f1 = __half22float2(*(__half2*)&rv.y);
            float2 f2 = __half22float2(*(__half2*)&rv.z);
            float2 f3 = __half22float2(*(__half2*)&rv.w);
            v0 = make_float4(f0.x, f0.y, f1.x, f1.y);
            v1 = make_float4(f2.x, f2.y, f3.x, f3.y);
        }
        *(float4*)&s[r][c8 * 8 + 4] = v0;
        *(float4*)&s[r][c8 * 8 + 8] = v1;
    }
    if (tid < DWR + 2) { s[tid][3] = 0.f; s[tid][WW + 4] = 0.f; }

    float w[9];
#pragma unroll
    for (int i = 0; i < 9; i++) w[i] = __ldg(&wdw[ch * 9 + i]);
    __syncthreads();

    const int lane = tid & 31;
    float nsq = 0.f;
    for (int r = tid >> 5; r < DWR; r += 8) {
        __half* orow = out + (size_t)bc * HW + (y0 + r) * WW;
#pragma unroll
        for (int j = 0; j < 4; j++) {
            int cc = lane + j * 32;
            float acc = 0.f;
#pragma unroll
            for (int dy = 0; dy < 3; dy++)
#pragma unroll
                for (int dx = 0; dx < 3; dx++)
                    acc += w[dy * 3 + dx] * s[r + dy][cc + 3 + dx];
            orow[cc] = __float2half_rn(acc);
            nsq += acc * acc;
        }
    }

    if (wantNorm) {
        // reduce 256 partials -> 1, deterministic tree within warps
#pragma unroll
        for (int o = 16; o > 0; o >>= 1)
            nsq += __shfl_xor_sync(0xffffffff, nsq, o);
        if (lane == 0) wred[tid >> 5] = nsq;
        __syncthreads();
        if (tid == 0) {
            float t = 0.f;
#pragma unroll
            for (int i = 0; i < 8; i++) t += wred[i];
            g_normp[((size_t)b * 2 * C + ch) * NBANDS + band] = t;
        }
    }
}

// ---------------------------------------------------------------------------
// Score partials via fp16 MMA — PURE MMA (sumsq moved to dw kernel).
// SPLIT=16: 8 iters of 128 spatial.
// ---------------------------------------------------------------------------
__device__ __forceinline__ int sc_slot(int r, int c) {  // [48 rows][16 chunks]
    return r * 16 + (c ^ (r & 7));
}

__global__ __launch_bounds__(256) void score_mma_kernel(const __half* __restrict__ qkvd)
{
    const int split = blockIdx.x;
    const int unit  = blockIdx.y;
    const int b = unit >> 2, hd = unit & 3;
    const __half* qb = qkvd + ((size_t)b * C3 + hd * CH) * HW;
    const __half* kb = qb + (size_t)C * HW;

    __shared__ __align__(16) uint4 Qs[CH * 16];
    __shared__ __align__(16) uint4 Ks[CH * 16];
    __shared__ float S[CH][CH];

    const int tid = threadIdx.x, lane = tid & 31, wid = tid >> 5;
    const unsigned qbase = (unsigned)__cvta_generic_to_shared(Qs);
    const unsigned kbase = (unsigned)__cvta_generic_to_shared(Ks);

    for (int e = tid; e < CH * CH; e += 256) S[e / CH][e % CH] = 0.f;

    float acc[3][6][4];
#pragma unroll
    for (int mi = 0; mi < 3; mi++)
#pragma unroll
        for (int ni = 0; ni < 6; ni++)
#pragma unroll
            for (int j = 0; j < 4; j++) acc[mi][ni][j] = 0.f;

    const int c0 = 2 * wid;
    const int ra = lane & 15;
    const int ca = lane >> 4;
    const int rb = (lane & 7) + ((lane >> 4) << 3);
    const int cbo = (lane >> 3) & 1;

#pragma unroll
    for (int it = 0; it < 8; it++) {
        const int s0 = split * 1024 + it * 128;
        __syncthreads();
#pragma unroll
        for (int i = 0; i < 3; i++) {
            int idx = tid + i * 256, r = idx >> 4, c = idx & 15;
            Qs[sc_slot(r, c)] = *(const uint4*)(const void*)&qb[(size_t)r * HW + s0 + c * 8];
            Ks[sc_slot(r, c)] = *(const uint4*)(const void*)&kb[(size_t)r * HW + s0 + c * 8];
        }
        __syncthreads();

        unsigned a[3][4];
#pragma unroll
        for (int mi = 0; mi < 3; mi++) {
            int r = 16 * mi + ra, c = c0 + ca;
            ldsm_x4(a[mi][0], a[mi][1], a[mi][2], a[mi][3],
                    qbase + (unsigned)(sc_slot(r, c) * 16));
        }
        unsigned bf[6][2];
#pragma unroll
        for (int nj = 0; nj < 3; nj++) {
            int r = 16 * nj + rb, c = c0 + cbo;
            ldsm_x4(bf[2*nj][0], bf[2*nj][1], bf[2*nj+1][0], bf[2*nj+1][1],
                    kbase + (unsigned)(sc_slot(r, c) * 16));
        }
#pragma unroll
        for (int mi = 0; mi < 3; mi++)
#pragma unroll
            for (int ni = 0; ni < 6; ni++)
                MMA_F16(acc[mi][ni], a[mi], bf[ni]);
    }

    __syncthreads();
#pragma unroll
    for (int mi = 0; mi < 3; mi++)
#pragma unroll
        for (int ni = 0; ni < 6; ni++)
#pragma unroll
            for (int d = 0; d < 4; d++) {
                int m = 16 * mi + (lane >> 2) + 8 * (d >> 1);
                int n = 8 * ni + (lane & 3) * 2 + (d & 1);
                atomicAdd(&S[m][n], acc[mi][ni][d]);
            }
    __syncthreads();

    float* part = g_part + ((size_t)split * NB * NH + unit) * PART_STRIDE;
    for (int e = tid; e < CH * CH; e += 256) part[e] = S[e / CH][e % CH];
}

// ---------------------------------------------------------------------------
// Reduce partials, normalize (norms from g_normp) + temperature + softmax.
// ---------------------------------------------------------------------------
__global__ __launch_bounds__(256) void softmax_kernel(const float* __restrict__ temperature)
{
    int unit = blockIdx.x;
    int b = unit >> 2, hd = unit & 3;
    __shared__ float S[CH][CH];
    __shared__ float rq[CH], rk[CH];
    int tid = threadIdx.x;

    for (int e = tid; e < CH * CH; e += 256) {
        float s = 0.f;
#pragma unroll
        for (int p = 0; p < SPLIT; p++)
            s += g_part[((size_t)p * NB * NH + unit) * PART_STRIDE + e];
        S[e / CH][e % CH] = s;
    }
    if (tid < 2 * CH) {
        int i = (tid < CH) ? tid : tid - CH;
        int ch = (tid < CH) ? (hd * CH + i) : (C + hd * CH + i);
        const float* np = g_normp + ((size_t)b * 2 * C + ch) * NBANDS;
        float s = 0.f;
#pragma unroll
        for (int p = 0; p < NBANDS; p++) s += np[p];
        float inv = 1.f / fmaxf(sqrtf(s), 1e-12f);
        if (tid < CH) rq[i] = inv; else rk[i] = inv;
    }
    __syncthreads();

    float temp = temperature[hd];
    if (tid < CH) {
        int i = tid;
        float row[CH];
        float mx = -3.402823466e38f;
#pragma unroll
        for (int j = 0; j < CH; j++) {
            float v = S[i][j] * rq[i] * rk[j] * temp;
            row[j] = v;
            mx = fmaxf(mx, v);
        }
        float sum = 0.f;
#pragma unroll
        for (int j = 0; j < CH; j++) { row[j] = expf(row[j] - mx); sum += row[j]; }
        float inv = 1.f / sum;
#pragma unroll
        for (int j = 0; j < CH; j++)
            g_score[(size_t)unit * CH * CH + i * CH + j] = row[j] * inv;
    }
}

// ---------------------------------------------------------------------------
// P_b[o, hd*48+d] = sum_c Wproj[o, hd*48+c] * score[c][d]  -> fp16 output.
// ---------------------------------------------------------------------------
__global__ __launch_bounds__(256) void pmat_kernel(const float* __restrict__ wproj)
{
    int unit = blockIdx.x;
    int b = unit >> 2, hd = unit & 3;
    __shared__ float sc[CH][CH];
    __shared__ float wp[C][CH];
    int tid = threadIdx.x;

    for (int e = tid; e < CH * CH; e += 256)
        sc[e / CH][e % CH] = g_score[(size_t)unit * CH * CH + e];
    for (int e = tid; e < C * CH; e += 256) {
        int o = e / CH, c = e % CH;
        wp[o][c] = wproj[o * C + hd * CH + c];
    }
    __syncthreads();

    for (int e = tid; e < C * CH; e += 256) {
        int o = e / CH, d = e % CH;
        float acc = 0.f;
#pragma unroll
        for (int c = 0; c < CH; c++) acc += wp[o][c] * sc[c][d];
        g_P[((size_t)b * C + o) * C + hd * CH + d] = __float2half_rn(acc);
    }
}

// ---------------------------------------------------------------------------
extern "C" void kernel_launch(void* const* d_in, const int* in_sizes, int n_in,
                              void* d_out, int out_size)
{
    (void)in_sizes; (void)n_in; (void)out_size;
    const float* x      = (const float*)d_in[0];
    const float* w_qkv  = (const float*)d_in[1];
    const float* w_dw   = (const float*)d_in[2];
    const float* w_proj = (const float*)d_in[3];
    const float* temp   = (const float*)d_in[4];
    float* out = (float*)d_out;

    __half *qkv, *dwb, *pmat;
    cudaGetSymbolAddress((void**)&qkv,  g_qkv);
    cudaGetSymbolAddress((void**)&dwb,  g_dw);
    cudaGetSymbolAddress((void**)&pmat, g_P);

    // Fork a side stream for the v-channel depthwise branch.
    cudaStream_t s2;
    cudaStreamCreateWithFlags(&s2, cudaStreamNonBlocking);
    cudaEvent_t ev1, ev2;
    cudaEventCreateWithFlags(&ev1, cudaEventDisableTiming);
    cudaEventCreateWithFlags(&ev2, cudaEventDisableTiming);

    // 1) qkv = W_qkv (576x192) * x[b] (192x16384)
    gemm_f32b_h_kernel<<<dim3(HW / GBN, C3 / GBM, NB), 256>>>(
        w_qkv, x, qkv, C3, HW, (size_t)KD * HW);
    cudaEventRecord(ev1, 0);
    cudaStreamWaitEvent(s2, ev1, 0);

    // 2a) depthwise on q,k channels + per-channel norms (main stream)
    dw_kernel<<<dim3(HH / DWR, NB * 2 * C), 256>>>(qkv, dwb, w_dw, 0, 2 * C, 1);
    // 2b) depthwise on v channels (side stream; feeds GEMM2 only)
    dw_kernel<<<dim3(HH / DWR, NB * C), 256, 0, s2>>>(qkv, dwb, w_dw, 2 * C, C, 0);
    cudaEventRecord(ev2, s2);

    // 3) split-K score partials (pure fp16 MMA, SPLIT=16)
    score_mma_kernel<<<dim3(SPLIT, NB * NH), 256>>>(dwb);
    // 4) normalize + temperature + softmax
    softmax_kernel<<<NB * NH, 256>>>(temp);
    // 5) P_b = W_proj @ blockdiag(score_b)  (fp16 out)
    pmat_kernel<<<NB * NH, 256>>>(w_proj);

    // join: GEMM2 needs dw(v)
    cudaStreamWaitEvent(0, ev2, 0);
    // 6) out = P_b (192x192) * v[b] (192x16384)
    gemm_hh_f32c_kernel<<<dim3(HW / GBN, C / GBM, NB), 256>>>(
        pmat, dwb + (size_t)2 * C * HW, out, C, HW,
        (size_t)C * C, (size_t)C3 * HW);

    cudaEventDestroy(ev1);
    cudaEventDestroy(ev2);
    cudaStreamDestroy(s2);
}